// round 1
// baseline (speedup 1.0000x reference)
#include <cuda_runtime.h>
#include <cstdint>
#include <cstddef>

#define TT 512
#define BB 16
#define EE 1024
#define HH 512
#define G3 1536

// pre-gate scratch [d][t][r][b] and per-(dir,step) completion counters
__device__ float g_preg[(size_t)2 * TT * G3 * BB];
__device__ int   g_cnt[2 * TT];

static __device__ __forceinline__ uint32_t f2tf(float f) {
    uint32_t r; asm("cvt.rna.tf32.f32 %0, %1;" : "=r"(r) : "f"(f)); return r;
}
static __device__ __forceinline__ float f2tff(float f) { return __uint_as_float(f2tf(f)); }

static __device__ __forceinline__ void mma8(float& d0, float& d1, float& d2, float& d3,
                                            uint32_t a0, uint32_t a1, uint32_t a2, uint32_t a3,
                                            uint32_t b0, uint32_t b1) {
    asm volatile(
        "mma.sync.aligned.m16n8k8.row.col.f32.tf32.tf32.f32 "
        "{%0,%1,%2,%3}, {%4,%5,%6,%7}, {%8,%9}, {%0,%1,%2,%3};"
        : "+f"(d0), "+f"(d1), "+f"(d2), "+f"(d3)
        : "r"(a0), "r"(a1), "r"(a2), "r"(a3), "r"(b0), "r"(b1));
}

static __device__ __forceinline__ int ld_acq(const int* p) {
    int v; asm volatile("ld.acquire.gpu.b32 %0, [%1];" : "=r"(v) : "l"(p) : "memory"); return v;
}

__global__ void zero_cnt_kernel() {
    int i = threadIdx.x;
    if (i < 2 * TT) g_cnt[i] = 0;
}

// ---------------------------------------------------------------------------
// Phase 1: pre-gates = x @ W_x^T + bias for both directions (tf32 mma GEMM)
// M = T*B = 8192 (row = t*16+b), N = 1536, K = 1024. Tiles: 128x64x32.
// ---------------------------------------------------------------------------
__global__ __launch_bounds__(256) void pregemm_kernel(
    const float* __restrict__ x,
    const float* __restrict__ wf, const float* __restrict__ bf,
    const float* __restrict__ wb, const float* __restrict__ bb) {
    const int d = blockIdx.z;
    const float* __restrict__ w    = d ? wb : wf;
    const float* __restrict__ bias = d ? bb : bf;
    const int row0 = blockIdx.y * 128;
    const int col0 = blockIdx.x * 64;

    __shared__ float As[128][36];  // [m][k], pad 36 -> conflict-free frag loads
    __shared__ float Bs[64][36];   // [n][k]

    const int tid = threadIdx.x;
    const int lane = tid & 31, wid = tid >> 5;
    const int wm = wid >> 1, wn = wid & 1;
    const int g = lane >> 2, t4 = lane & 3;

    float acc[2][4][4];
#pragma unroll
    for (int i = 0; i < 2; i++)
#pragma unroll
        for (int j = 0; j < 4; j++)
#pragma unroll
            for (int r = 0; r < 4; r++) acc[i][j][r] = 0.f;

    for (int k0 = 0; k0 < EE; k0 += 32) {
#pragma unroll
        for (int i = 0; i < 4; i++) {
            int idx = tid + i * 256;
            int m = idx >> 3, kq = idx & 7;
            int row = row0 + m;
            int t = row >> 4, b = row & 15;
            float4 v = *reinterpret_cast<const float4*>(
                x + (size_t)(b * TT + t) * EE + k0 + kq * 4);
            float4 o = make_float4(f2tff(v.x), f2tff(v.y), f2tff(v.z), f2tff(v.w));
            *reinterpret_cast<float4*>(&As[m][kq * 4]) = o;
        }
#pragma unroll
        for (int i = 0; i < 2; i++) {
            int idx = tid + i * 256;
            int n = idx >> 3, kq = idx & 7;
            float4 v = *reinterpret_cast<const float4*>(
                w + (size_t)(col0 + n) * G3 + k0 + kq * 4);
            float4 o = make_float4(f2tff(v.x), f2tff(v.y), f2tff(v.z), f2tff(v.w));
            *reinterpret_cast<float4*>(&Bs[n][kq * 4]) = o;
        }
        __syncthreads();

#pragma unroll
        for (int kt = 0; kt < 4; kt++) {
            int k = kt * 8;
            uint32_t a[2][4];
#pragma unroll
            for (int mt = 0; mt < 2; mt++) {
                int mb = wm * 32 + mt * 16;
                a[mt][0] = __float_as_uint(As[mb + g][k + t4]);
                a[mt][1] = __float_as_uint(As[mb + g + 8][k + t4]);
                a[mt][2] = __float_as_uint(As[mb + g][k + 4 + t4]);
                a[mt][3] = __float_as_uint(As[mb + g + 8][k + 4 + t4]);
            }
#pragma unroll
            for (int nt = 0; nt < 4; nt++) {
                int nb = wn * 32 + nt * 8;
                uint32_t b0 = __float_as_uint(Bs[nb + g][k + t4]);
                uint32_t b1 = __float_as_uint(Bs[nb + g][k + 4 + t4]);
#pragma unroll
                for (int mt = 0; mt < 2; mt++)
                    mma8(acc[mt][nt][0], acc[mt][nt][1], acc[mt][nt][2], acc[mt][nt][3],
                         a[mt][0], a[mt][1], a[mt][2], a[mt][3], b0, b1);
            }
        }
        __syncthreads();
    }

#pragma unroll
    for (int mt = 0; mt < 2; mt++) {
        int rowb = row0 + wm * 32 + mt * 16 + g;
#pragma unroll
        for (int nt = 0; nt < 4; nt++) {
            int colb = col0 + wn * 32 + nt * 8 + 2 * t4;
#pragma unroll
            for (int r = 0; r < 4; r++) {
                int row = rowb + ((r >= 2) ? 8 : 0);
                int col = colb + (r & 1);
                int t = row >> 4, b = row & 15;
                float v = acc[mt][nt][r] + __ldg(bias + col);
                g_preg[(((size_t)d * TT + t) * G3 + col) * BB + b] = v;
            }
        }
    }
}

// ---------------------------------------------------------------------------
// Phase 2: persistent recurrence. 128 CTAs (64/dir, all resident), 128 thr.
// Each CTA: 8 h-columns => 24 gate rows (i/j/o), W_h tf32 in SMEM.
// Per step: flag-wait -> load h_{t-1} (from d_out) -> 4-warp K-split mma
// -> smem reduce -> cell update -> h to d_out -> fence + release counter.
// ---------------------------------------------------------------------------
#define NWROWS 24
#define WPAD 516
#define RPAD 33

__global__ __launch_bounds__(128) void recur_kernel(
    const float* __restrict__ wf, const float* __restrict__ wb,
    const float* __restrict__ h0f, const float* __restrict__ h0b,
    const float* __restrict__ c0f, const float* __restrict__ c0b,
    float* __restrict__ out) {
    extern __shared__ float sm[];
    float* Wsm = sm;                     // 24*516
    float* hsm = Wsm + NWROWS * WPAD;    // 16*516
    float* red = hsm + 16 * WPAD;        // 4*16*33 = 2112

    const int d   = (int)blockIdx.x >> 6;
    const int grp = (int)blockIdx.x & 63;
    const int n0  = grp * 8;
    const float* __restrict__ w  = d ? wb : wf;
    const float* __restrict__ h0 = d ? h0b : h0f;
    const float* __restrict__ c0 = d ? c0b : c0f;
    const float* __restrict__ preg = g_preg + (size_t)d * TT * G3 * BB;
    int* cnt = g_cnt + d * TT;

    const int tid = threadIdx.x, lane = tid & 31, wid = tid >> 5;
    const int g = lane >> 2, t4 = lane & 3;
    const int eb = tid >> 3, en = tid & 7;  // epilogue (batch, col) ownership

    // Load this block's 24 W_h rows (k in [1024,1536) of W) as tf32 into SMEM
    for (int idx = tid; idx < NWROWS * 128; idx += 128) {
        int j = idx >> 7, kq = idx & 127;
        int r = (j < 8) ? (n0 + j) : ((j < 16) ? (512 + n0 + j - 8) : (1024 + n0 + j - 16));
        float4 v = *reinterpret_cast<const float4*>(w + (size_t)r * G3 + 1024 + kq * 4);
        float4 o = make_float4(f2tff(v.x), f2tff(v.y), f2tff(v.z), f2tff(v.w));
        *reinterpret_cast<float4*>(&Wsm[j * WPAD + kq * 4]) = o;
    }
    float c = c0[n0 + en];  // cell state lives in a register all 512 steps
    __syncthreads();

    for (int s = 0; s < TT; s++) {
        const int tt = d ? (TT - 1 - s) : s;

        if (s > 0) {
            if (tid == 0) {
                while (ld_acq(cnt + s - 1) < 64) {}
            }
            __syncthreads();
        }

        // fill hsm[16][512] with h_{t-1} (tf32-rounded)
        if (s == 0) {
            for (int idx = tid; idx < 16 * 128; idx += 128) {
                int b = idx >> 7, kq = idx & 127;
                float4 v = *reinterpret_cast<const float4*>(h0 + kq * 4);
                float4 o = make_float4(f2tff(v.x), f2tff(v.y), f2tff(v.z), f2tff(v.w));
                *reinterpret_cast<float4*>(&hsm[b * WPAD + kq * 4]) = o;
            }
        } else {
            const int tp = d ? (tt + 1) : (tt - 1);
            for (int idx = tid; idx < 16 * 128; idx += 128) {
                int b = idx >> 7, kq = idx & 127;
                float4 v = *reinterpret_cast<const float4*>(
                    out + (size_t)(b * TT + tp) * 1024 + d * 512 + kq * 4);
                float4 o = make_float4(f2tff(v.x), f2tff(v.y), f2tff(v.z), f2tff(v.w));
                *reinterpret_cast<float4*>(&hsm[b * WPAD + kq * 4]) = o;
            }
        }
        __syncthreads();

        // prefetch this thread's pre-gate values (hides L2 latency under mma)
        float pgi = __ldg(preg + ((size_t)tt * G3 + (n0 + en)) * BB + eb);
        float pgj = __ldg(preg + ((size_t)tt * G3 + (512 + n0 + en)) * BB + eb);
        float pgo = __ldg(preg + ((size_t)tt * G3 + (1024 + n0 + en)) * BB + eb);

        // 4-warp K-split: warp wid covers k in [wid*128, wid*128+128)
        float acc[3][4];
#pragma unroll
        for (int nt = 0; nt < 3; nt++)
#pragma unroll
            for (int r = 0; r < 4; r++) acc[nt][r] = 0.f;

        const int kbase = wid * 128;
#pragma unroll
        for (int kt = 0; kt < 16; kt++) {
            int k = kbase + kt * 8;
            uint32_t a0 = __float_as_uint(hsm[g * WPAD + k + t4]);
            uint32_t a1 = __float_as_uint(hsm[(g + 8) * WPAD + k + t4]);
            uint32_t a2 = __float_as_uint(hsm[g * WPAD + k + 4 + t4]);
            uint32_t a3 = __float_as_uint(hsm[(g + 8) * WPAD + k + 4 + t4]);
#pragma unroll
            for (int nt = 0; nt < 3; nt++) {
                uint32_t b0 = __float_as_uint(Wsm[(nt * 8 + g) * WPAD + k + t4]);
                uint32_t b1 = __float_as_uint(Wsm[(nt * 8 + g) * WPAD + k + 4 + t4]);
                mma8(acc[nt][0], acc[nt][1], acc[nt][2], acc[nt][3],
                     a0, a1, a2, a3, b0, b1);
            }
        }

        // stash partials for cross-warp K reduction
#pragma unroll
        for (int nt = 0; nt < 3; nt++) {
            int rl = nt * 8 + 2 * t4;
            red[wid * 528 + g * RPAD + rl]           = acc[nt][0];
            red[wid * 528 + g * RPAD + rl + 1]       = acc[nt][1];
            red[wid * 528 + (g + 8) * RPAD + rl]     = acc[nt][2];
            red[wid * 528 + (g + 8) * RPAD + rl + 1] = acc[nt][3];
        }
        __syncthreads();

        // epilogue: each thread owns exactly one (b, n) output
        float si = pgi, sj = pgj, so = pgo;
#pragma unroll
        for (int wq = 0; wq < 4; wq++) {
            si += red[wq * 528 + eb * RPAD + en];
            sj += red[wq * 528 + eb * RPAD + 8 + en];
            so += red[wq * 528 + eb * RPAD + 16 + en];
        }
        float ig = 1.f / (1.f + __expf(-si));
        float cj = tanhf(sj);
        c = (1.f - ig) * c + ig * cj;                       // coupled gate
        float h = tanhf(c) * (1.f / (1.f + __expf(-so)));
        out[(size_t)(eb * TT + tt) * 1024 + d * 512 + n0 + en] = h;

        __threadfence();
        __syncthreads();
        if (tid == 0) atomicAdd(cnt + s, 1);  // release: h of step s published
    }
}

extern "C" void kernel_launch(void* const* d_in, const int* in_sizes, int n_in,
                              void* d_out, int out_size) {
    (void)in_sizes; (void)n_in; (void)out_size;
    const float* x   = (const float*)d_in[0];
    const float* wf  = (const float*)d_in[1];
    const float* bf  = (const float*)d_in[2];
    const float* wb  = (const float*)d_in[3];
    const float* bb  = (const float*)d_in[4];
    const float* h0f = (const float*)d_in[5];
    const float* h0b = (const float*)d_in[6];
    const float* c0f = (const float*)d_in[7];
    const float* c0b = (const float*)d_in[8];
    float* out = (float*)d_out;

    const int smem_bytes = (NWROWS * WPAD + 16 * WPAD + 4 * 528) * 4;  // 91008
    cudaFuncSetAttribute(recur_kernel, cudaFuncAttributeMaxDynamicSharedMemorySize,
                         smem_bytes);

    zero_cnt_kernel<<<1, 1024>>>();
    dim3 g1(G3 / 64, (TT * BB) / 128, 2);
    pregemm_kernel<<<g1, 256>>>(x, wf, bf, wb, bb);
    recur_kernel<<<128, 128, smem_bytes>>>(wf, wb, h0f, h0b, c0f, c0b, out);
}